// round 4
// baseline (speedup 1.0000x reference)
#include <cuda_runtime.h>

// LengthRegulator, fused single kernel (gather formulation), FLOAT32 output.
//
//   cs = inclusive cumsum(dur[b]);  out[b,p] = (p < cs[N-1]) ? searchsorted_right(cs, p)+1 : 0
//
// Key change vs previous rounds: output written as float32 (harness __output__
// dtype), not int32. Values 0..4096 are exactly representable in fp32.
//
// Grid: B * nblk CTAs, 256 threads. CTA (b, chunk) recomputes row b's cumsum
// into shared (redundant across chunks but L2-resident), then binary-searches
// its 2048-element output slice. Every output element written exactly once.

#define N_TOK       4096
#define THREADS     256
#define PER_THREAD  (N_TOK / THREADS)      // 16 tokens per thread
#define OUT_PER_CTA 2048                   // 8 outputs per thread

__global__ __launch_bounds__(THREADS)
void lr_fused_kernel(const int* __restrict__ dur,
                     float* __restrict__ out,
                     int T, int nblk) {
    const int b     = blockIdx.x / nblk;
    const int chunk = blockIdx.x % nblk;
    const int tid   = threadIdx.x;
    const int lane  = tid & 31;
    const int wid   = tid >> 5;

    __shared__ int s_cs[N_TOK];
    __shared__ int s_wsum[THREADS / 32];
    __shared__ int s_woff[THREADS / 32];

    // ---- 1) load 16 contiguous durations per thread, local inclusive scan ----
    int v[PER_THREAD];
    {
        const int4* d4 = (const int4*)(dur + b * N_TOK) + tid * 4;
        int4 a = d4[0], c = d4[1], e = d4[2], f = d4[3];
        v[0]  = a.x; v[1]  = a.y; v[2]  = a.z; v[3]  = a.w;
        v[4]  = c.x; v[5]  = c.y; v[6]  = c.z; v[7]  = c.w;
        v[8]  = e.x; v[9]  = e.y; v[10] = e.z; v[11] = e.w;
        v[12] = f.x; v[13] = f.y; v[14] = f.z; v[15] = f.w;
    }
    #pragma unroll
    for (int i = 1; i < PER_THREAD; i++) v[i] += v[i - 1];
    const int my_total = v[PER_THREAD - 1];

    // ---- 2) warp inclusive scan of per-thread totals ----
    int s = my_total;
    #pragma unroll
    for (int o = 1; o < 32; o <<= 1) {
        int u = __shfl_up_sync(0xffffffffu, s, o);
        if (lane >= o) s += u;
    }
    if (lane == 31) s_wsum[wid] = s;
    __syncthreads();

    // ---- 3) tiny serial scan of the 8 warp totals ----
    if (tid == 0) {
        int acc = 0;
        #pragma unroll
        for (int w = 0; w < THREADS / 32; w++) {
            s_woff[w] = acc;
            acc += s_wsum[w];
        }
    }
    __syncthreads();

    const int base = s_woff[wid] + (s - my_total);   // exclusive prefix for this thread

    // ---- 4) publish inclusive cumsum ----
    #pragma unroll
    for (int i = 0; i < PER_THREAD; i++) {
        s_cs[tid * PER_THREAD + i] = base + v[i];
    }
    __syncthreads();

    // ---- 5) gather: binary search each output position ----
    const int total = s_cs[N_TOK - 1];
    const int p0    = chunk * OUT_PER_CTA;
    float* orow = out + b * T;

    #pragma unroll
    for (int k = 0; k < OUT_PER_CTA / THREADS; k++) {
        const int p = p0 + k * THREADS + tid;          // coalesced across the warp
        if (p < T) {
            // first index with s_cs[idx] > p   (== searchsorted side='right')
            int lo = 0, hi = N_TOK;
            #pragma unroll
            for (int it = 0; it < 12; it++) {          // 2^12 == 4096
                const int mid = (lo + hi) >> 1;
                if (s_cs[mid] > p) hi = mid; else lo = mid + 1;
            }
            orow[p] = (p < total) ? (float)(lo + 1) : 0.0f;
        }
    }
}

extern "C" void kernel_launch(void* const* d_in, const int* in_sizes, int n_in,
                              void* d_out, int out_size) {
    const int* dur = (const int*)d_in[0];
    float*     out = (float*)d_out;
    const int  B   = 32;
    const int  T   = out_size / B;
    const int  nblk = (T + OUT_PER_CTA - 1) / OUT_PER_CTA;

    lr_fused_kernel<<<B * nblk, THREADS>>>(dur, out, T, nblk);
}

// round 6
// speedup vs baseline: 1.1920x; 1.1920x over previous
#include <cuda_runtime.h>

// LengthRegulator, fused kernel v2.1: cumsum + scatter-into-shared-tile + scalar store.
//
//   cs = inclusive cumsum(dur[b]);  out[b,p] = (p < cs[N-1]) ? searchsorted_right(cs,p)+1 : 0
//
// v1 (12.3us) = binary search per output element (latency-bound).
// v2 inverts it: token t owns run [cs[t-1], cs[t]); scatter values into a zeroed
// shared tile, then stream out. v2.1 fixes v2's fault: T is not a multiple of 4,
// so row bases (out + b*T) are not 16B-aligned -> float4 STG faulted. Scalar
// 4B coalesced stores instead (DRAM was 0.6%, vector width irrelevant).

#define N_TOK       4096
#define THREADS     256
#define PER_THREAD  (N_TOK / THREADS)      // 16 tokens per thread
#define OUT_PER_CTA 2048

__global__ __launch_bounds__(THREADS)
void lr_scatter_kernel(const int* __restrict__ dur,
                       float* __restrict__ out,
                       int T, int nblk) {
    const int b     = blockIdx.x / nblk;
    const int chunk = blockIdx.x % nblk;
    const int tid   = threadIdx.x;
    const int lane  = tid & 31;
    const int wid   = tid >> 5;

    __shared__ int   s_cs[N_TOK];
    __shared__ float s_out[OUT_PER_CTA];
    __shared__ int   s_wsum[THREADS / 32];
    __shared__ int   s_woff[THREADS / 32];

    // ---- 1) load 16 contiguous durations per thread, local inclusive scan ----
    int v[PER_THREAD];
    {
        const int4* d4 = (const int4*)(dur + b * N_TOK) + tid * 4;
        int4 a = d4[0], c = d4[1], e = d4[2], f = d4[3];
        v[0]  = a.x; v[1]  = a.y; v[2]  = a.z; v[3]  = a.w;
        v[4]  = c.x; v[5]  = c.y; v[6]  = c.z; v[7]  = c.w;
        v[8]  = e.x; v[9]  = e.y; v[10] = e.z; v[11] = e.w;
        v[12] = f.x; v[13] = f.y; v[14] = f.z; v[15] = f.w;
    }
    #pragma unroll
    for (int i = 1; i < PER_THREAD; i++) v[i] += v[i - 1];
    const int my_total = v[PER_THREAD - 1];

    // ---- 2) warp inclusive scan of per-thread totals ----
    int s = my_total;
    #pragma unroll
    for (int o = 1; o < 32; o <<= 1) {
        int u = __shfl_up_sync(0xffffffffu, s, o);
        if (lane >= o) s += u;
    }
    if (lane == 31) s_wsum[wid] = s;

    // zero the output tile while the scan settles (8 floats / thread)
    #pragma unroll
    for (int k = 0; k < OUT_PER_CTA / THREADS; k++)
        s_out[k * THREADS + tid] = 0.0f;
    __syncthreads();

    // ---- 3) serial scan of the 8 warp totals ----
    if (tid == 0) {
        int acc = 0;
        #pragma unroll
        for (int w = 0; w < THREADS / 32; w++) { s_woff[w] = acc; acc += s_wsum[w]; }
    }
    __syncthreads();

    const int base = s_woff[wid] + (s - my_total);   // exclusive prefix for this thread

    // ---- 4) publish inclusive cumsum ----
    #pragma unroll
    for (int i = 0; i < PER_THREAD; i++)
        s_cs[tid * PER_THREAD + i] = base + v[i];
    __syncthreads();

    // ---- 5) scatter token values into the shared tile ----
    const int total = s_cs[N_TOK - 1];
    const int p0    = chunk * OUT_PER_CTA;
    int p1 = p0 + OUT_PER_CTA;
    if (p1 > T)     p1 = T;
    if (p1 > total) p1 = total;

    if (p0 < p1) {
        // first token with cs[t] > p0 — all threads follow the same path
        // (broadcast LDS, conflict-free), 12 steps once per CTA.
        int lo = 0, hi = N_TOK;
        #pragma unroll
        for (int it = 0; it < 12; it++) {
            const int mid = (lo + hi) >> 1;
            if (s_cs[mid] > p0) hi = mid; else lo = mid + 1;
        }
        // tokens strided across threads; monotone cs => per-thread break is safe
        for (int t = lo + tid; t < N_TOK; t += THREADS) {
            const int st = (t == 0) ? 0 : s_cs[t - 1];
            if (st >= p1) break;
            const int en = (s_cs[t] < p1) ? s_cs[t] : p1;
            const float val = (float)(t + 1);
            for (int p = (st > p0 ? st : p0); p < en; p++)
                s_out[p - p0] = val;
        }
    }
    __syncthreads();

    // ---- 6) stream the tile to global, scalar coalesced (alignment-proof) ----
    float* orow = out + b * T;
    #pragma unroll
    for (int k = 0; k < OUT_PER_CTA / THREADS; k++) {
        const int idx = k * THREADS + tid;
        const int p   = p0 + idx;
        if (p < T) orow[p] = s_out[idx];
    }
}

extern "C" void kernel_launch(void* const* d_in, const int* in_sizes, int n_in,
                              void* d_out, int out_size) {
    const int* dur = (const int*)d_in[0];
    float*     out = (float*)d_out;
    const int  B    = 32;
    const int  T    = out_size / B;
    const int  nblk = (T + OUT_PER_CTA - 1) / OUT_PER_CTA;

    lr_scatter_kernel<<<B * nblk, THREADS>>>(dur, out, T, nblk);
}